// round 15
// baseline (speedup 1.0000x reference)
#include <cuda_runtime.h>
#include <math.h>

#define SEQ 16384
#define NGC 1536          // gate cols computed (f-gate skipped)
#define TT 20
#define NEGV -10000.0f
#define START_T 18
#define STOP_T 19

typedef unsigned int u32;
typedef unsigned long long u64;

// ---------------- scratch (device globals, allocation-free) ----------------
__device__ float g_gates[(size_t)SEQ * NGC];              // 100.7 MB
__device__ float g_enc[(size_t)SEQ * 512];                // 33.6 MB
__device__ float g_feats[(size_t)SEQ * TT];               // 1.31 MB
__device__ float g_fv[(size_t)SEQ * TT];                  // 1.31 MB (fv entering step t)
__device__ unsigned char g_bp[(size_t)SEQ * TT];          // 327 KB
__device__ unsigned char g_cand[(size_t)128 * TT * 128];  // 327 KB
__device__ unsigned char g_map[128 * TT];
__device__ int g_ent[128];
__device__ int g_best;

// ---------------- K1: gate GEMM with FFMA2 (fp32x2 packed) ----------------
// G[m][n], n-layout [i_f|g_f|o_f|i_b|g_b|o_b] (256 each).
// 128x128x16 tiles, 256 threads, 8x8 microtile packed as 4 row-pairs x 8 cols.
__global__ void __launch_bounds__(256, 2) k_gemm(
    const float* __restrict__ X,   // tok base: x + 768
    const float* __restrict__ Wf,
    const float* __restrict__ Wb)
{
    __shared__ float  As[16][128];      // [k][m]
    __shared__ float2 Bs[16][128];      // [k][swizzled n], value duplicated in .x/.y

    const int tid = threadIdx.x;
    const int m0 = blockIdx.y * 128;
    const int n0 = blockIdx.x * 128;
    const int tx = tid & 15;
    const int ty = tid >> 4;

    const float* aptr[2];
    const float* bptr[2];
    int arow[2], akq[2], bcolS[2], bkq[2];
#pragma unroll
    for (int u = 0; u < 2; u++) {
        int idx = tid + u * 256;        // 0..511
        arow[u] = idx >> 2;
        akq[u]  = idx & 3;
        aptr[u] = X + (size_t)(m0 + arow[u]) * 768 + akq[u] * 4;
        int bcol = idx >> 2;
        bkq[u]  = idx & 3;
        bcolS[u] = (bcol & 3) * 32 + (bcol >> 2);   // swizzle: conflict-free compute loads
        int n = n0 + bcol;
        int dir = (n >= 768) ? 1 : 0;
        int mm = n - dir * 768;
        int row = mm + ((mm >= 256) ? 256 : 0);     // i:[0,256) g:[512,768) o:[768,1024)
        bptr[u] = (dir ? Wb : Wf) + (size_t)row * 768 + bkq[u] * 4;
    }

    u64 acc[4][8];                      // [row-pair][col], each = (f32,f32)
#pragma unroll
    for (int r = 0; r < 4; r++)
#pragma unroll
        for (int c = 0; c < 8; c++) acc[r][c] = 0ull;

    for (int kt = 0; kt < 48; kt++) {
        float4 av[2], bv[2];
#pragma unroll
        for (int u = 0; u < 2; u++) {
            av[u] = *(const float4*)(aptr[u] + kt * 16);
            bv[u] = *(const float4*)(bptr[u] + kt * 16);
        }
        __syncthreads();
#pragma unroll
        for (int u = 0; u < 2; u++) {
            As[akq[u] * 4 + 0][arow[u]] = av[u].x;
            As[akq[u] * 4 + 1][arow[u]] = av[u].y;
            As[akq[u] * 4 + 2][arow[u]] = av[u].z;
            As[akq[u] * 4 + 3][arow[u]] = av[u].w;
            Bs[bkq[u] * 4 + 0][bcolS[u]] = make_float2(bv[u].x, bv[u].x);
            Bs[bkq[u] * 4 + 1][bcolS[u]] = make_float2(bv[u].y, bv[u].y);
            Bs[bkq[u] * 4 + 2][bcolS[u]] = make_float2(bv[u].z, bv[u].z);
            Bs[bkq[u] * 4 + 3][bcolS[u]] = make_float2(bv[u].w, bv[u].w);
        }
        __syncthreads();
#pragma unroll
        for (int k = 0; k < 16; k++) {
            u64 a2[4], b2[8];
            a2[0] = *(const u64*)&As[k][ty * 4];
            a2[1] = *(const u64*)&As[k][ty * 4 + 2];
            a2[2] = *(const u64*)&As[k][64 + ty * 4];
            a2[3] = *(const u64*)&As[k][64 + ty * 4 + 2];
#pragma unroll
            for (int c = 0; c < 4; c++) {
                b2[c]     = *(const u64*)&Bs[k][c * 32 + tx];
                b2[4 + c] = *(const u64*)&Bs[k][c * 32 + 16 + tx];
            }
#pragma unroll
            for (int r = 0; r < 4; r++)
#pragma unroll
                for (int c = 0; c < 8; c++)
                    asm("fma.rn.f32x2 %0,%1,%2,%0;" : "+l"(acc[r][c]) : "l"(a2[r]), "l"(b2[c]));
        }
    }

    // epilogue: unpack row pairs, store float4s
#pragma unroll
    for (int rp = 0; rp < 4; rp++) {
        int mrow = m0 + ((rp >= 2) ? 64 : 0) + ty * 4 + (rp & 1) * 2;
        float lo[8], hi[8];
#pragma unroll
        for (int c = 0; c < 8; c++)
            asm("mov.b64 {%0,%1},%2;" : "=f"(lo[c]), "=f"(hi[c]) : "l"(acc[rp][c]));
        float* o0 = g_gates + (size_t)mrow * NGC + n0;
        float* o1 = g_gates + (size_t)(mrow + 1) * NGC + n0;
        *(float4*)(o0 + tx * 4)      = make_float4(lo[0], lo[1], lo[2], lo[3]);
        *(float4*)(o0 + 64 + tx * 4) = make_float4(lo[4], lo[5], lo[6], lo[7]);
        *(float4*)(o1 + tx * 4)      = make_float4(hi[0], hi[1], hi[2], hi[3]);
        *(float4*)(o1 + 64 + tx * 4) = make_float4(hi[4], hi[5], hi[6], hi[7]);
    }
}

// ---------------- K2: activations -> enc ----------------
__global__ void k_act(const float* __restrict__ bihf, const float* __restrict__ bhhf,
                      const float* __restrict__ bihb, const float* __restrict__ bhhb)
{
    int idx = blockIdx.x * blockDim.x + threadIdx.x;
    if (idx >= SEQ * 512) return;
    int m = idx >> 9;
    int c = idx & 511;
    int dir = c >> 8;
    int ch = c & 255;
    const float* G = g_gates + (size_t)m * NGC + dir * 768;
    const float* bi = dir ? bihb : bihf;
    const float* bh = dir ? bhhb : bhhf;
    float gi = (G[ch]        + bi[ch])        + bh[ch];
    float gg = (G[256 + ch]  + bi[512 + ch])  + bh[512 + ch];
    float go = (G[512 + ch]  + bi[768 + ch])  + bh[768 + ch];
    float si = 1.0f / (1.0f + expf(-gi));
    float so = 1.0f / (1.0f + expf(-go));
    float cc = si * tanhf(gg);
    g_enc[(size_t)m * 512 + c] = so * tanhf(cc);
}

// ---------------- K3: feats = enc @ w_tag.T + b_tag (round-12 proven version) ----
__global__ void __launch_bounds__(256) k_feats(const float* __restrict__ Wt,
                                               const float* __restrict__ bt)
{
    __shared__ float es[64][68];
    __shared__ float ws[20][68];
    const int tid = threadIdx.x;
    const int m0 = blockIdx.x * 64;
    float acc[5] = {0.f, 0.f, 0.f, 0.f, 0.f};

    for (int kc = 0; kc < 512; kc += 64) {
        __syncthreads();
#pragma unroll
        for (int u = 0; u < 4; u++) {
            int idx = tid + u * 256;            // 0..1023 float4 slots
            int row = idx >> 4, kq = idx & 15;
            float4 v = *(const float4*)(g_enc + (size_t)(m0 + row) * 512 + kc + kq * 4);
            *(float4*)&es[row][kq * 4] = v;
        }
#pragma unroll
        for (int u = 0; u < 2; u++) {
            int idx = tid + u * 256;
            if (idx < 320) {                    // 20*16 float4 slots
                int row = idx >> 4, kq = idx & 15;
                float4 v = *(const float4*)(Wt + (size_t)row * 512 + kc + kq * 4);
                *(float4*)&ws[row][kq * 4] = v;
            }
        }
        __syncthreads();
#pragma unroll
        for (int q = 0; q < 5; q++) {
            int o = tid * 5 + q;
            int tok = o / 20, tag = o % 20;
            float a = acc[q];
#pragma unroll
            for (int k = 0; k < 64; k++) a = fmaf(es[tok][k], ws[tag][k], a);
            acc[q] = a;
        }
    }
#pragma unroll
    for (int q = 0; q < 5; q++) {
        int o = tid * 5 + q;
        int tok = o / 20, tag = o % 20;
        g_feats[(size_t)(m0 + tok) * TT + tag] = acc[q] + bt[tag];
    }
}

// ---------------- K4: serial Viterbi forward, values only (1 warp) ----------------
__device__ __forceinline__ float vstep(float fv, const float tr[TT], float feat,
                                       int t, int j, bool act)
{
    if (act) g_fv[(size_t)t * TT + j] = fv;    // fv entering step t (for parallel bp)
    float ss[TT];
#pragma unroll
    for (int i = 0; i < TT; i++)
        ss[i] = __shfl_sync(0xffffffffu, fv, i) + tr[i];
#pragma unroll
    for (int q = 0; q < 10; q++) ss[q] = fmaxf(ss[2 * q], ss[2 * q + 1]);
#pragma unroll
    for (int q = 0; q < 5; q++)  ss[q] = fmaxf(ss[2 * q], ss[2 * q + 1]);
    ss[0] = fmaxf(ss[0], ss[1]);
    ss[1] = fmaxf(ss[2], ss[3]);
    ss[0] = fmaxf(ss[0], ss[1]);
    ss[0] = fmaxf(ss[0], ss[4]);
    return ss[0] + feat;
}

__global__ void k_vit(const float* __restrict__ trans, float* __restrict__ out, int off)
{
    const int j = threadIdx.x;
    const bool act = (j < TT);
    float tr[TT];
#pragma unroll
    for (int i = 0; i < TT; i++) tr[i] = act ? trans[j * TT + i] : NEGV;
    float fv = (j == START_T) ? 0.0f : NEGV;

#define LDF(t) (act ? __ldg(&g_feats[(size_t)(t) * TT + j]) : 0.0f)
    float f0 = LDF(0), f1 = LDF(1), f2 = LDF(2), f3 = LDF(3);
    for (int t = 0; t < SEQ; t += 4) {
        int p = (t + 4 < SEQ) ? (t + 4) : (SEQ - 4);
        float n0 = LDF(p + 0), n1 = LDF(p + 1), n2 = LDF(p + 2), n3 = LDF(p + 3);
        fv = vstep(fv, tr, f0, t + 0, j, act);
        fv = vstep(fv, tr, f1, t + 1, j, act);
        fv = vstep(fv, tr, f2, t + 2, j, act);
        fv = vstep(fv, tr, f3, t + 3, j, act);
        f0 = n0; f1 = n1; f2 = n2; f3 = n3;
    }
#undef LDF

    float term = act ? (fv + trans[STOP_T * TT + j]) : NEGV;
    float best = NEGV * 4.0f;
    int bj = 0;
#pragma unroll
    for (int i = 0; i < TT; i++) {
        float v = __shfl_sync(0xffffffffu, term, i);
        if (v > best) { best = v; bj = i; }
    }
    if (j == 0) {
        g_best = bj;
        if (off) out[0] = best;
    }
}

// ---------------- K4b: parallel backpointer recompute ----------------
// bp[t][j] = argmax_i(fv_t[i] + tr[j][i]) with lowest-index tie-break (strict >,
// keep-left, ascending contiguous pairing — matches jnp.argmax).
__global__ void __launch_bounds__(256) k_bp(const float* __restrict__ trans)
{
    __shared__ float trs[TT * TT];
    const int lt = threadIdx.x;             // lane 0..31
    const int wy = threadIdx.y;             // warp 0..7, one token each
    const int tid = wy * 32 + lt;
    for (int i = tid; i < TT * TT; i += 256) trs[i] = trans[i];
    __syncthreads();

    const int t = blockIdx.x * 8 + wy;
    const int j = lt;
    const bool act = (j < TT);
    float fvl = (lt < TT) ? g_fv[(size_t)t * TT + lt] : NEGV;

    float ss[TT];
    int ii[TT];
#pragma unroll
    for (int i = 0; i < TT; i++) {
        float v = __shfl_sync(0xffffffffu, fvl, i);
        ss[i] = v + (act ? trs[j * TT + i] : 0.0f);
        ii[i] = i;
    }
#define CMB(d, a, b) { bool p = ss[b] > ss[a]; ss[d] = p ? ss[b] : ss[a]; ii[d] = p ? ii[b] : ii[a]; }
#pragma unroll
    for (int q = 0; q < 10; q++) CMB(q, 2 * q, 2 * q + 1);
#pragma unroll
    for (int q = 0; q < 5; q++)  CMB(q, 2 * q, 2 * q + 1);
    CMB(0, 0, 1); CMB(1, 2, 3); ss[2] = ss[4]; ii[2] = ii[4];
    CMB(0, 0, 1); ss[1] = ss[2]; ii[1] = ii[2];
    CMB(0, 0, 1);
#undef CMB
    if (act) g_bp[(size_t)t * TT + j] = (unsigned char)ii[0];
}

// ---------------- K5: backtrack phase A (chunk candidates + maps) ----------------
__global__ void k_bt1()
{
    __shared__ unsigned char bl[128 * TT];
    const int c = blockIdx.x;
    const int t0 = c * 128;
    const u32* src = (const u32*)(g_bp + (size_t)t0 * TT);
    u32* dst = (u32*)bl;
    for (int i = threadIdx.x; i < 640; i += 32) dst[i] = src[i];
    __syncwarp();
    int s = threadIdx.x;
    if (s < TT) {
        int cur = s;
        unsigned char* cand = g_cand + ((size_t)c * TT + s) * 128;
        cand[127] = (unsigned char)cur;
        for (int r = 127; r >= 1; r--) {
            cur = bl[r * TT + cur];
            cand[r - 1] = (unsigned char)cur;
        }
        g_map[c * TT + s] = bl[cur];
    }
}

// ---------------- K6: backtrack phase B (serial chunk stitch) ----------------
__global__ void k_bt2()
{
    __shared__ unsigned char mp[128 * TT];
    u32* dst = (u32*)mp;
    const u32* src = (const u32*)g_map;
    for (int i = threadIdx.x; i < 640; i += 32) dst[i] = src[i];
    __syncwarp();
    if (threadIdx.x == 0) {
        int e = g_best;
        g_ent[127] = e;
        for (int c = 127; c >= 1; c--) {
            e = mp[c * TT + e];
            g_ent[c - 1] = e;
        }
    }
}

// ---------------- K7: backtrack phase C (emit path) ----------------
__global__ void k_bt3(float* __restrict__ out, int off)
{
    int c = blockIdx.x, r = threadIdx.x;
    int e = g_ent[c];
    out[off + c * 128 + r] = (float)g_cand[((size_t)c * TT + e) * 128 + r];
}

// ---------------- launcher ----------------
extern "C" void kernel_launch(void* const* d_in, const int* in_sizes, int n_in,
                              void* d_out, int out_size)
{
    const float* x     = (const float*)d_in[0];
    const float* wihf  = (const float*)d_in[1];
    const float* bihf  = (const float*)d_in[3];
    const float* bhhf  = (const float*)d_in[4];
    const float* wihb  = (const float*)d_in[5];
    const float* bihb  = (const float*)d_in[7];
    const float* bhhb  = (const float*)d_in[8];
    const float* wtag  = (const float*)d_in[9];
    const float* btag  = (const float*)d_in[10];
    const float* trans = (const float*)d_in[11];
    float* out = (float*)d_out;

    int off = (out_size >= SEQ + 1) ? 1 : 0;

    dim3 gg(NGC / 128, SEQ / 128);
    k_gemm<<<gg, 256>>>(x + 768, wihf, wihb);
    k_act<<<(SEQ * 512) / 256, 256>>>(bihf, bhhf, bihb, bhhb);
    k_feats<<<SEQ / 64, 256>>>(wtag, btag);
    k_vit<<<1, 32>>>(trans, out, off);
    k_bp<<<SEQ / 8, dim3(32, 8)>>>(trans);
    k_bt1<<<128, 32>>>();
    k_bt2<<<1, 32>>>();
    k_bt3<<<128, 128>>>(out, off);
}

// round 16
// speedup vs baseline: 1.1099x; 1.1099x over previous
#include <cuda_runtime.h>
#include <math.h>

#define SEQ 16384
#define NGC 1536          // gate cols computed (f-gate skipped)
#define TT 20
#define NEGV -10000.0f
#define START_T 18
#define STOP_T 19
#define NT 12             // n tiles per slab  (1536/128)
#define MT 128            // m tiles = slabs   (16384/128)
#define TILES (NT * MT)

typedef unsigned int u32;
typedef unsigned long long u64;

// ---------------- scratch (device globals, allocation-free) ----------------
__device__ float g_gates[(size_t)SEQ * NGC];              // 100.7 MB
__device__ float g_enc[(size_t)SEQ * 512];                // 33.6 MB
__device__ float g_feats[(size_t)SEQ * TT];               // 1.31 MB
__device__ float g_fv[(size_t)SEQ * TT];                  // 1.31 MB
__device__ unsigned char g_bp[(size_t)SEQ * TT];          // 327 KB
__device__ unsigned char g_cand[(size_t)128 * TT * 128];  // 327 KB
__device__ unsigned char g_map[128 * TT];
__device__ int g_ent[128];
__device__ int g_best;
__device__ int g_ticket;
__device__ int g_slab_done[MT];
__device__ int g_slab_ready[MT];

// ---------------- init: reset progress state every call ----------------
__global__ void k_init()
{
    int i = threadIdx.x;
    if (i == 0) g_ticket = 0;
    if (i < MT) { g_slab_done[i] = 0; g_slab_ready[i] = 0; }
}

// ---------------- GEMM tile (FFMA2, proven in round 14) ----------------
// G[m][n], n-layout [i_f|g_f|o_f|i_b|g_b|o_b] (256 each).
__device__ __forceinline__ void gemm_tile(int m0, int n0,
    const float* __restrict__ X, const float* __restrict__ Wf, const float* __restrict__ Wb,
    float (*As)[128], float2 (*Bs)[128])
{
    const int tid = threadIdx.x;
    const int tx = tid & 15;
    const int ty = tid >> 4;

    const float* aptr[2];
    const float* bptr[2];
    int arow[2], akq[2], bcolS[2], bkq[2];
#pragma unroll
    for (int u = 0; u < 2; u++) {
        int idx = tid + u * 256;        // 0..511
        arow[u] = idx >> 2;
        akq[u]  = idx & 3;
        aptr[u] = X + (size_t)(m0 + arow[u]) * 768 + akq[u] * 4;
        int bcol = idx >> 2;
        bkq[u]  = idx & 3;
        bcolS[u] = (bcol & 3) * 32 + (bcol >> 2);
        int n = n0 + bcol;
        int dir = (n >= 768) ? 1 : 0;
        int mm = n - dir * 768;
        int row = mm + ((mm >= 256) ? 256 : 0);
        bptr[u] = (dir ? Wb : Wf) + (size_t)row * 768 + bkq[u] * 4;
    }

    u64 acc[4][8];
#pragma unroll
    for (int r = 0; r < 4; r++)
#pragma unroll
        for (int c = 0; c < 8; c++) acc[r][c] = 0ull;

    for (int kt = 0; kt < 48; kt++) {
        float4 av[2], bv[2];
#pragma unroll
        for (int u = 0; u < 2; u++) {
            av[u] = *(const float4*)(aptr[u] + kt * 16);
            bv[u] = *(const float4*)(bptr[u] + kt * 16);
        }
        __syncthreads();
#pragma unroll
        for (int u = 0; u < 2; u++) {
            As[akq[u] * 4 + 0][arow[u]] = av[u].x;
            As[akq[u] * 4 + 1][arow[u]] = av[u].y;
            As[akq[u] * 4 + 2][arow[u]] = av[u].z;
            As[akq[u] * 4 + 3][arow[u]] = av[u].w;
            Bs[bkq[u] * 4 + 0][bcolS[u]] = make_float2(bv[u].x, bv[u].x);
            Bs[bkq[u] * 4 + 1][bcolS[u]] = make_float2(bv[u].y, bv[u].y);
            Bs[bkq[u] * 4 + 2][bcolS[u]] = make_float2(bv[u].z, bv[u].z);
            Bs[bkq[u] * 4 + 3][bcolS[u]] = make_float2(bv[u].w, bv[u].w);
        }
        __syncthreads();
#pragma unroll
        for (int k = 0; k < 16; k++) {
            u64 a2[4], b2[8];
            a2[0] = *(const u64*)&As[k][ty * 4];
            a2[1] = *(const u64*)&As[k][ty * 4 + 2];
            a2[2] = *(const u64*)&As[k][64 + ty * 4];
            a2[3] = *(const u64*)&As[k][64 + ty * 4 + 2];
#pragma unroll
            for (int c = 0; c < 4; c++) {
                b2[c]     = *(const u64*)&Bs[k][c * 32 + tx];
                b2[4 + c] = *(const u64*)&Bs[k][c * 32 + 16 + tx];
            }
#pragma unroll
            for (int r = 0; r < 4; r++)
#pragma unroll
                for (int c = 0; c < 8; c++)
                    asm("fma.rn.f32x2 %0,%1,%2,%0;" : "+l"(acc[r][c]) : "l"(a2[r]), "l"(b2[c]));
        }
    }

#pragma unroll
    for (int rp = 0; rp < 4; rp++) {
        int mrow = m0 + ((rp >= 2) ? 64 : 0) + ty * 4 + (rp & 1) * 2;
        float lo[8], hi[8];
#pragma unroll
        for (int c = 0; c < 8; c++)
            asm("mov.b64 {%0,%1},%2;" : "=f"(lo[c]), "=f"(hi[c]) : "l"(acc[rp][c]));
        float* o0 = g_gates + (size_t)mrow * NGC + n0;
        float* o1 = g_gates + (size_t)(mrow + 1) * NGC + n0;
        *(float4*)(o0 + tx * 4)      = make_float4(lo[0], lo[1], lo[2], lo[3]);
        *(float4*)(o0 + 64 + tx * 4) = make_float4(lo[4], lo[5], lo[6], lo[7]);
        *(float4*)(o1 + tx * 4)      = make_float4(hi[0], hi[1], hi[2], hi[3]);
        *(float4*)(o1 + 64 + tx * 4) = make_float4(hi[4], hi[5], hi[6], hi[7]);
    }
}

// ---------------- per-slab activation (block-wide, 128 tokens) ----------------
__device__ __forceinline__ void act_slab(int m0,
    const float* __restrict__ bihf, const float* __restrict__ bhhf,
    const float* __restrict__ bihb, const float* __restrict__ bhhb)
{
    for (int i = threadIdx.x; i < 128 * 512; i += 256) {
        int m = m0 + (i >> 9);
        int c = i & 511;
        int dir = c >> 8;
        int ch = c & 255;
        const float* G = g_gates + (size_t)m * NGC + dir * 768;
        const float* bi = dir ? bihb : bihf;
        const float* bh = dir ? bhhb : bhhf;
        float gi = (G[ch]       + bi[ch])       + bh[ch];
        float gg = (G[256 + ch] + bi[512 + ch]) + bh[512 + ch];
        float go = (G[512 + ch] + bi[768 + ch]) + bh[768 + ch];
        float si = 1.0f / (1.0f + expf(-gi));
        float so = 1.0f / (1.0f + expf(-go));
        float cc = si * tanhf(gg);
        g_enc[(size_t)m * 512 + c] = so * tanhf(cc);
    }
}

// ---------------- per-64-token feats (round-12 proven body) ----------------
__device__ __forceinline__ void feats_slab(int m0,
    const float* __restrict__ Wt, const float* __restrict__ bt,
    float (*es)[68], float (*ws)[68])
{
    const int tid = threadIdx.x;
    float acc[5] = {0.f, 0.f, 0.f, 0.f, 0.f};

    for (int kc = 0; kc < 512; kc += 64) {
        __syncthreads();
#pragma unroll
        for (int u = 0; u < 4; u++) {
            int idx = tid + u * 256;
            int row = idx >> 4, kq = idx & 15;
            float4 v = *(const float4*)(g_enc + (size_t)(m0 + row) * 512 + kc + kq * 4);
            *(float4*)&es[row][kq * 4] = v;
        }
#pragma unroll
        for (int u = 0; u < 2; u++) {
            int idx = tid + u * 256;
            if (idx < 320) {
                int row = idx >> 4, kq = idx & 15;
                float4 v = *(const float4*)(Wt + (size_t)row * 512 + kc + kq * 4);
                *(float4*)&ws[row][kq * 4] = v;
            }
        }
        __syncthreads();
#pragma unroll
        for (int q = 0; q < 5; q++) {
            int o = tid * 5 + q;
            int tok = o / 20, tag = o % 20;
            float a = acc[q];
#pragma unroll
            for (int k = 0; k < 64; k++) a = fmaf(es[tok][k], ws[tag][k], a);
            acc[q] = a;
        }
    }
#pragma unroll
    for (int q = 0; q < 5; q++) {
        int o = tid * 5 + q;
        int tok = o / 20, tag = o % 20;
        g_feats[(size_t)(m0 + tok) * TT + tag] = acc[q] + bt[tag];
    }
}

// ---------------- Viterbi step (values only, exact) ----------------
__device__ __forceinline__ float vstep(float fv, const float tr[TT], float feat,
                                       int t, int j, bool act)
{
    if (act) g_fv[(size_t)t * TT + j] = fv;
    float ss[TT];
#pragma unroll
    for (int i = 0; i < TT; i++)
        ss[i] = __shfl_sync(0xffffffffu, fv, i) + tr[i];
#pragma unroll
    for (int q = 0; q < 10; q++) ss[q] = fmaxf(ss[2 * q], ss[2 * q + 1]);
#pragma unroll
    for (int q = 0; q < 5; q++)  ss[q] = fmaxf(ss[2 * q], ss[2 * q + 1]);
    ss[0] = fmaxf(ss[0], ss[1]);
    ss[1] = fmaxf(ss[2], ss[3]);
    ss[0] = fmaxf(ss[0], ss[1]);
    ss[0] = fmaxf(ss[0], ss[4]);
    return ss[0] + feat;
}

// ---------------- fused persistent kernel ----------------
__global__ void __launch_bounds__(256, 2) k_fused(
    const float* __restrict__ X,   // tok base: x + 768
    const float* __restrict__ Wf, const float* __restrict__ Wb,
    const float* __restrict__ bihf, const float* __restrict__ bhhf,
    const float* __restrict__ bihb, const float* __restrict__ bhhb,
    const float* __restrict__ Wt, const float* __restrict__ bt,
    const float* __restrict__ trans, float* __restrict__ out, int off)
{
    __shared__ __align__(16) unsigned char smraw[24576];
    __shared__ int s_flag;

    if (blockIdx.x == 0) {
        // ---------------- consumer: single Viterbi warp ----------------
        if (threadIdx.x >= 32) return;
        const int j = threadIdx.x;
        const bool act = (j < TT);
        float tr[TT];
#pragma unroll
        for (int i = 0; i < TT; i++) tr[i] = act ? trans[j * TT + i] : NEGV;
        float fv = (j == START_T) ? 0.0f : NEGV;

        for (int s = 0; s < MT; s++) {
            if (j == 0) {
                while (atomicAdd(&g_slab_ready[s], 0) == 0) __nanosleep(128);
            }
            __syncwarp();
            __threadfence();
            const int base = s * 128;
#define LDF(t) (act ? __ldg(&g_feats[(size_t)(t) * TT + j]) : 0.0f)
            float f0 = LDF(base), f1 = LDF(base + 1), f2 = LDF(base + 2), f3 = LDF(base + 3);
            for (int t = base; t < base + 128; t += 4) {
                int p = (t + 4 < base + 128) ? (t + 4) : (base + 124);
                float n0 = LDF(p), n1 = LDF(p + 1), n2 = LDF(p + 2), n3 = LDF(p + 3);
                fv = vstep(fv, tr, f0, t + 0, j, act);
                fv = vstep(fv, tr, f1, t + 1, j, act);
                fv = vstep(fv, tr, f2, t + 2, j, act);
                fv = vstep(fv, tr, f3, t + 3, j, act);
                f0 = n0; f1 = n1; f2 = n2; f3 = n3;
            }
#undef LDF
        }

        float term = act ? (fv + trans[STOP_T * TT + j]) : NEGV;
        float best = NEGV * 4.0f;
        int bj = 0;
#pragma unroll
        for (int i = 0; i < TT; i++) {
            float v = __shfl_sync(0xffffffffu, term, i);
            if (v > best) { best = v; bj = i; }
        }
        if (j == 0) {
            g_best = bj;
            if (off) out[0] = best;
        }
        return;
    }

    // ---------------- producers: GEMM tiles + slab act/feats ----------------
    float  (*As)[128] = (float  (*)[128])smraw;            //  8 KB
    float2 (*Bs)[128] = (float2 (*)[128])(smraw + 8192);   // 16 KB
    float  (*es)[68]  = (float  (*)[68])smraw;             // 17.4 KB
    float  (*ws)[68]  = (float  (*)[68])(smraw + 17408);   //  5.4 KB

    for (;;) {
        if (threadIdx.x == 0) s_flag = atomicAdd(&g_ticket, 1);
        __syncthreads();
        int t = s_flag;
        __syncthreads();
        if (t >= TILES) break;
        int m = t / NT, n = t % NT;

        gemm_tile(m * 128, n * 128, X, Wf, Wb, As, Bs);
        __syncthreads();                       // all tile stores issued

        if (threadIdx.x == 0) {
            __threadfence();                   // release tile stores
            int d = atomicAdd(&g_slab_done[m], 1);
            s_flag = (d == NT - 1) ? 1 : 0;
        }
        __syncthreads();
        if (s_flag) {
            __threadfence();                   // acquire other blocks' tile stores
            act_slab(m * 128, bihf, bhhf, bihb, bhhb);
            __syncthreads();
            feats_slab(m * 128, Wt, bt, es, ws);
            feats_slab(m * 128 + 64, Wt, bt, es, ws);
            __syncthreads();
            if (threadIdx.x == 0) {
                __threadfence();               // release feats
                atomicExch(&g_slab_ready[m], 1);
            }
        }
        __syncthreads();
    }
}

// ---------------- parallel backpointer recompute ----------------
__global__ void __launch_bounds__(256) k_bp(const float* __restrict__ trans)
{
    __shared__ float trs[TT * TT];
    const int lt = threadIdx.x;
    const int wy = threadIdx.y;
    const int tid = wy * 32 + lt;
    for (int i = tid; i < TT * TT; i += 256) trs[i] = trans[i];
    __syncthreads();

    const int t = blockIdx.x * 8 + wy;
    const int j = lt;
    const bool act = (j < TT);
    float fvl = (lt < TT) ? g_fv[(size_t)t * TT + lt] : NEGV;

    float ss[TT];
    int ii[TT];
#pragma unroll
    for (int i = 0; i < TT; i++) {
        float v = __shfl_sync(0xffffffffu, fvl, i);
        ss[i] = v + (act ? trs[j * TT + i] : 0.0f);
        ii[i] = i;
    }
#define CMB(d, a, b) { bool p = ss[b] > ss[a]; ss[d] = p ? ss[b] : ss[a]; ii[d] = p ? ii[b] : ii[a]; }
#pragma unroll
    for (int q = 0; q < 10; q++) CMB(q, 2 * q, 2 * q + 1);
#pragma unroll
    for (int q = 0; q < 5; q++)  CMB(q, 2 * q, 2 * q + 1);
    CMB(0, 0, 1); CMB(1, 2, 3); ss[2] = ss[4]; ii[2] = ii[4];
    CMB(0, 0, 1); ss[1] = ss[2]; ii[1] = ii[2];
    CMB(0, 0, 1);
#undef CMB
    if (act) g_bp[(size_t)t * TT + j] = (unsigned char)ii[0];
}

// ---------------- backtrack: chunk candidates + maps ----------------
__global__ void k_bt1()
{
    __shared__ unsigned char bl[128 * TT];
    const int c = blockIdx.x;
    const int t0 = c * 128;
    const u32* src = (const u32*)(g_bp + (size_t)t0 * TT);
    u32* dst = (u32*)bl;
    for (int i = threadIdx.x; i < 640; i += 32) dst[i] = src[i];
    __syncwarp();
    int s = threadIdx.x;
    if (s < TT) {
        int cur = s;
        unsigned char* cand = g_cand + ((size_t)c * TT + s) * 128;
        cand[127] = (unsigned char)cur;
        for (int r = 127; r >= 1; r--) {
            cur = bl[r * TT + cur];
            cand[r - 1] = (unsigned char)cur;
        }
        g_map[c * TT + s] = bl[cur];
    }
}

__global__ void k_bt2()
{
    __shared__ unsigned char mp[128 * TT];
    u32* dst = (u32*)mp;
    const u32* src = (const u32*)g_map;
    for (int i = threadIdx.x; i < 640; i += 32) dst[i] = src[i];
    __syncwarp();
    if (threadIdx.x == 0) {
        int e = g_best;
        g_ent[127] = e;
        for (int c = 127; c >= 1; c--) {
            e = mp[c * TT + e];
            g_ent[c - 1] = e;
        }
    }
}

__global__ void k_bt3(float* __restrict__ out, int off)
{
    int c = blockIdx.x, r = threadIdx.x;
    int e = g_ent[c];
    out[off + c * 128 + r] = (float)g_cand[((size_t)c * TT + e) * 128 + r];
}

// ---------------- launcher ----------------
extern "C" void kernel_launch(void* const* d_in, const int* in_sizes, int n_in,
                              void* d_out, int out_size)
{
    const float* x     = (const float*)d_in[0];
    const float* wihf  = (const float*)d_in[1];
    const float* bihf  = (const float*)d_in[3];
    const float* bhhf  = (const float*)d_in[4];
    const float* wihb  = (const float*)d_in[5];
    const float* bihb  = (const float*)d_in[7];
    const float* bhhb  = (const float*)d_in[8];
    const float* wtag  = (const float*)d_in[9];
    const float* btag  = (const float*)d_in[10];
    const float* trans = (const float*)d_in[11];
    float* out = (float*)d_out;

    int off = (out_size >= SEQ + 1) ? 1 : 0;

    k_init<<<1, 128>>>();
    k_fused<<<297, 256>>>(x + 768, wihf, wihb, bihf, bhhf, bihb, bhhb,
                          wtag, btag, trans, out, off);
    k_bp<<<SEQ / 8, dim3(32, 8)>>>(trans);
    k_bt1<<<128, 32>>>();
    k_bt2<<<1, 32>>>();
    k_bt3<<<128, 128>>>(out, off);
}

// round 17
// speedup vs baseline: 1.2761x; 1.1497x over previous
#include <cuda_runtime.h>
#include <math.h>

#define SEQ 16384
#define NGC 1536          // gate cols computed (f-gate skipped)
#define TT 20
#define NEGV -10000.0f
#define START_T 18
#define STOP_T 19
#define NT 12             // n tiles per slab  (1536/128)
#define MT 128            // m tiles = slabs   (16384/128)
#define TILES (NT * MT)

typedef unsigned int u32;
typedef unsigned long long u64;

// ---------------- scratch (device globals, allocation-free) ----------------
__device__ float g_gates[(size_t)SEQ * NGC];              // 100.7 MB
__device__ float g_enc[(size_t)SEQ * 512];                // 33.6 MB
__device__ float g_feats[(size_t)SEQ * TT];               // 1.31 MB
__device__ float g_fv[(size_t)SEQ * TT];                  // 1.31 MB
__device__ unsigned char g_bp[(size_t)SEQ * TT];          // 327 KB
__device__ unsigned char g_cand[(size_t)128 * TT * 128];  // 327 KB
__device__ unsigned char g_map[128 * TT];
__device__ int g_ent[128];
__device__ int g_best;
__device__ int g_ticket;
__device__ int g_slab_done[MT];
__device__ int g_slab_ready[MT];
__device__ int g_vit_smid;

// ---------------- init: reset progress state every call ----------------
__global__ void k_init()
{
    int i = threadIdx.x;
    if (i == 0) { g_ticket = 0; g_vit_smid = -1; }
    if (i < MT) { g_slab_done[i] = 0; g_slab_ready[i] = 0; }
}

// ---------------- GEMM tile (FFMA2, proven) ----------------
// G[m][n], n-layout [i_f|g_f|o_f|i_b|g_b|o_b] (256 each).
__device__ __forceinline__ void gemm_tile(int m0, int n0,
    const float* __restrict__ X, const float* __restrict__ Wf, const float* __restrict__ Wb,
    float (*As)[128], float2 (*Bs)[128])
{
    const int tid = threadIdx.x;
    const int tx = tid & 15;
    const int ty = tid >> 4;

    const float* aptr[2];
    const float* bptr[2];
    int arow[2], akq[2], bcolS[2], bkq[2];
#pragma unroll
    for (int u = 0; u < 2; u++) {
        int idx = tid + u * 256;        // 0..511
        arow[u] = idx >> 2;
        akq[u]  = idx & 3;
        aptr[u] = X + (size_t)(m0 + arow[u]) * 768 + akq[u] * 4;
        int bcol = idx >> 2;
        bkq[u]  = idx & 3;
        bcolS[u] = (bcol & 3) * 32 + (bcol >> 2);
        int n = n0 + bcol;
        int dir = (n >= 768) ? 1 : 0;
        int mm = n - dir * 768;
        int row = mm + ((mm >= 256) ? 256 : 0);
        bptr[u] = (dir ? Wb : Wf) + (size_t)row * 768 + bkq[u] * 4;
    }

    u64 acc[4][8];
#pragma unroll
    for (int r = 0; r < 4; r++)
#pragma unroll
        for (int c = 0; c < 8; c++) acc[r][c] = 0ull;

    for (int kt = 0; kt < 48; kt++) {
        float4 av[2], bv[2];
#pragma unroll
        for (int u = 0; u < 2; u++) {
            av[u] = *(const float4*)(aptr[u] + kt * 16);
            bv[u] = *(const float4*)(bptr[u] + kt * 16);
        }
        __syncthreads();
#pragma unroll
        for (int u = 0; u < 2; u++) {
            As[akq[u] * 4 + 0][arow[u]] = av[u].x;
            As[akq[u] * 4 + 1][arow[u]] = av[u].y;
            As[akq[u] * 4 + 2][arow[u]] = av[u].z;
            As[akq[u] * 4 + 3][arow[u]] = av[u].w;
            Bs[bkq[u] * 4 + 0][bcolS[u]] = make_float2(bv[u].x, bv[u].x);
            Bs[bkq[u] * 4 + 1][bcolS[u]] = make_float2(bv[u].y, bv[u].y);
            Bs[bkq[u] * 4 + 2][bcolS[u]] = make_float2(bv[u].z, bv[u].z);
            Bs[bkq[u] * 4 + 3][bcolS[u]] = make_float2(bv[u].w, bv[u].w);
        }
        __syncthreads();
#pragma unroll
        for (int k = 0; k < 16; k++) {
            u64 a2[4], b2[8];
            a2[0] = *(const u64*)&As[k][ty * 4];
            a2[1] = *(const u64*)&As[k][ty * 4 + 2];
            a2[2] = *(const u64*)&As[k][64 + ty * 4];
            a2[3] = *(const u64*)&As[k][64 + ty * 4 + 2];
#pragma unroll
            for (int c = 0; c < 4; c++) {
                b2[c]     = *(const u64*)&Bs[k][c * 32 + tx];
                b2[4 + c] = *(const u64*)&Bs[k][c * 32 + 16 + tx];
            }
#pragma unroll
            for (int r = 0; r < 4; r++)
#pragma unroll
                for (int c = 0; c < 8; c++)
                    asm("fma.rn.f32x2 %0,%1,%2,%0;" : "+l"(acc[r][c]) : "l"(a2[r]), "l"(b2[c]));
        }
    }

#pragma unroll
    for (int rp = 0; rp < 4; rp++) {
        int mrow = m0 + ((rp >= 2) ? 64 : 0) + ty * 4 + (rp & 1) * 2;
        float lo[8], hi[8];
#pragma unroll
        for (int c = 0; c < 8; c++)
            asm("mov.b64 {%0,%1},%2;" : "=f"(lo[c]), "=f"(hi[c]) : "l"(acc[rp][c]));
        float* o0 = g_gates + (size_t)mrow * NGC + n0;
        float* o1 = g_gates + (size_t)(mrow + 1) * NGC + n0;
        *(float4*)(o0 + tx * 4)      = make_float4(lo[0], lo[1], lo[2], lo[3]);
        *(float4*)(o0 + 64 + tx * 4) = make_float4(lo[4], lo[5], lo[6], lo[7]);
        *(float4*)(o1 + tx * 4)      = make_float4(hi[0], hi[1], hi[2], hi[3]);
        *(float4*)(o1 + 64 + tx * 4) = make_float4(hi[4], hi[5], hi[6], hi[7]);
    }
}

// ---------------- per-slab activation (block-wide, 128 tokens) ----------------
__device__ __forceinline__ void act_slab(int m0,
    const float* __restrict__ bihf, const float* __restrict__ bhhf,
    const float* __restrict__ bihb, const float* __restrict__ bhhb)
{
    for (int i = threadIdx.x; i < 128 * 512; i += 256) {
        int m = m0 + (i >> 9);
        int c = i & 511;
        int dir = c >> 8;
        int ch = c & 255;
        const float* G = g_gates + (size_t)m * NGC + dir * 768;
        const float* bi = dir ? bihb : bihf;
        const float* bh = dir ? bhhb : bhhf;
        float gi = (G[ch]       + bi[ch])       + bh[ch];
        float gg = (G[256 + ch] + bi[512 + ch]) + bh[512 + ch];
        float go = (G[512 + ch] + bi[768 + ch]) + bh[768 + ch];
        float si = 1.0f / (1.0f + expf(-gi));
        float so = 1.0f / (1.0f + expf(-go));
        float cc = si * tanhf(gg);
        g_enc[(size_t)m * 512 + c] = so * tanhf(cc);
    }
}

// ---------------- per-64-token feats ----------------
__device__ __forceinline__ void feats_slab(int m0,
    const float* __restrict__ Wt, const float* __restrict__ bt,
    float (*es)[68], float (*ws)[68])
{
    const int tid = threadIdx.x;
    float acc[5] = {0.f, 0.f, 0.f, 0.f, 0.f};

    for (int kc = 0; kc < 512; kc += 64) {
        __syncthreads();
#pragma unroll
        for (int u = 0; u < 4; u++) {
            int idx = tid + u * 256;
            int row = idx >> 4, kq = idx & 15;
            float4 v = *(const float4*)(g_enc + (size_t)(m0 + row) * 512 + kc + kq * 4);
            *(float4*)&es[row][kq * 4] = v;
        }
#pragma unroll
        for (int u = 0; u < 2; u++) {
            int idx = tid + u * 256;
            if (idx < 320) {
                int row = idx >> 4, kq = idx & 15;
                float4 v = *(const float4*)(Wt + (size_t)row * 512 + kc + kq * 4);
                *(float4*)&ws[row][kq * 4] = v;
            }
        }
        __syncthreads();
#pragma unroll
        for (int q = 0; q < 5; q++) {
            int o = tid * 5 + q;
            int tok = o / 20, tag = o % 20;
            float a = acc[q];
#pragma unroll
            for (int k = 0; k < 64; k++) a = fmaf(es[tok][k], ws[tag][k], a);
            acc[q] = a;
        }
    }
#pragma unroll
    for (int q = 0; q < 5; q++) {
        int o = tid * 5 + q;
        int tok = o / 20, tag = o % 20;
        g_feats[(size_t)(m0 + tok) * TT + tag] = acc[q] + bt[tag];
    }
}

// ---------------- fused persistent kernel ----------------
__global__ void __launch_bounds__(256, 2) k_fused(
    const float* __restrict__ X,   // tok base: x + 768
    const float* __restrict__ Wf, const float* __restrict__ Wb,
    const float* __restrict__ bihf, const float* __restrict__ bhhf,
    const float* __restrict__ bihb, const float* __restrict__ bhhb,
    const float* __restrict__ Wt, const float* __restrict__ bt,
    const float* __restrict__ trans, float* __restrict__ out, int off)
{
    __shared__ __align__(16) unsigned char smraw[24576];
    __shared__ __align__(16) float vbuf[2][32];
    __shared__ int s_flag;

    if (blockIdx.x == 0) {
        // ---------------- consumer: single Viterbi warp, own SM ----------------
        if (threadIdx.x >= 32) return;
        const int j = threadIdx.x;
        if (j == 0) {
            unsigned smid;
            asm("mov.u32 %0, %%smid;" : "=r"(smid));
            atomicExch(&g_vit_smid, (int)smid);
            __threadfence();
        }
        const bool act = (j < TT);
        float tr[TT];
#pragma unroll
        for (int i = 0; i < TT; i++) tr[i] = act ? trans[j * TT + i] : NEGV;
        float fv = (j == START_T) ? 0.0f : NEGV;

        for (int s = 0; s < MT; s++) {
            if (j == 0) {
                while (atomicAdd(&g_slab_ready[s], 0) == 0) __nanosleep(128);
            }
            __syncwarp();
            __threadfence();
            const int base = s * 128;
#define LDF(t) (act ? __ldg(&g_feats[(size_t)(t) * TT + j]) : 0.0f)
#define VSTEP(t, par, feat) do {                                              \
            if (act) g_fv[(size_t)(t) * TT + j] = fv;                         \
            vbuf[par][j] = fv;                                                \
            __syncwarp();                                                     \
            float4 v0 = *(const float4*)&vbuf[par][0];                        \
            float4 v1 = *(const float4*)&vbuf[par][4];                        \
            float4 v2 = *(const float4*)&vbuf[par][8];                        \
            float4 v3 = *(const float4*)&vbuf[par][12];                       \
            float4 v4 = *(const float4*)&vbuf[par][16];                       \
            float ss[TT];                                                     \
            ss[0]=v0.x+tr[0];  ss[1]=v0.y+tr[1];  ss[2]=v0.z+tr[2];           \
            ss[3]=v0.w+tr[3];  ss[4]=v1.x+tr[4];  ss[5]=v1.y+tr[5];           \
            ss[6]=v1.z+tr[6];  ss[7]=v1.w+tr[7];  ss[8]=v2.x+tr[8];           \
            ss[9]=v2.y+tr[9];  ss[10]=v2.z+tr[10]; ss[11]=v2.w+tr[11];        \
            ss[12]=v3.x+tr[12]; ss[13]=v3.y+tr[13]; ss[14]=v3.z+tr[14];       \
            ss[15]=v3.w+tr[15]; ss[16]=v4.x+tr[16]; ss[17]=v4.y+tr[17];       \
            ss[18]=v4.z+tr[18]; ss[19]=v4.w+tr[19];                           \
            _Pragma("unroll")                                                 \
            for (int q = 0; q < 10; q++) ss[q] = fmaxf(ss[2*q], ss[2*q+1]);   \
            _Pragma("unroll")                                                 \
            for (int q = 0; q < 5; q++)  ss[q] = fmaxf(ss[2*q], ss[2*q+1]);   \
            ss[0] = fmaxf(ss[0], ss[1]);                                      \
            ss[1] = fmaxf(ss[2], ss[3]);                                      \
            ss[0] = fmaxf(ss[0], ss[1]);                                      \
            ss[0] = fmaxf(ss[0], ss[4]);                                      \
            fv = ss[0] + (feat);                                              \
        } while (0)

            float f0 = LDF(base), f1 = LDF(base + 1), f2 = LDF(base + 2), f3 = LDF(base + 3);
            for (int t = base; t < base + 128; t += 4) {
                int p = (t + 4 < base + 128) ? (t + 4) : (base + 124);
                float n0 = LDF(p), n1 = LDF(p + 1), n2 = LDF(p + 2), n3 = LDF(p + 3);
                VSTEP(t + 0, 0, f0);
                VSTEP(t + 1, 1, f1);
                VSTEP(t + 2, 0, f2);
                VSTEP(t + 3, 1, f3);
                f0 = n0; f1 = n1; f2 = n2; f3 = n3;
            }
#undef VSTEP
#undef LDF
        }

        float term = act ? (fv + trans[STOP_T * TT + j]) : NEGV;
        float best = NEGV * 4.0f;
        int bj = 0;
#pragma unroll
        for (int i = 0; i < TT; i++) {
            float v = __shfl_sync(0xffffffffu, term, i);
            if (v > best) { best = v; bj = i; }
        }
        if (j == 0) {
            g_best = bj;
            if (off) out[0] = best;
        }
        return;
    }

    // ---------------- producers: GEMM tiles + slab act/feats ----------------
    float  (*As)[128] = (float  (*)[128])smraw;            //  8 KB
    float2 (*Bs)[128] = (float2 (*)[128])(smraw + 8192);   // 16 KB
    float  (*es)[68]  = (float  (*)[68])smraw;             // 17.4 KB
    float  (*ws)[68]  = (float  (*)[68])(smraw + 17408);   //  5.4 KB

    unsigned mysm;
    asm("mov.u32 %0, %%smid;" : "=r"(mysm));

    for (;;) {
        if (threadIdx.x == 0) {
            // vacate the consumer's SM (checked BEFORE taking a ticket)
            int vs = atomicAdd(&g_vit_smid, 0);
            s_flag = (vs == (int)mysm) ? -1 : atomicAdd(&g_ticket, 1);
        }
        __syncthreads();
        int t = s_flag;
        __syncthreads();
        if (t < 0 || t >= TILES) break;
        int m = t / NT, n = t % NT;

        gemm_tile(m * 128, n * 128, X, Wf, Wb, As, Bs);
        __syncthreads();                       // all tile stores issued

        if (threadIdx.x == 0) {
            __threadfence();                   // release tile stores
            int d = atomicAdd(&g_slab_done[m], 1);
            s_flag = (d == NT - 1) ? 1 : 0;
        }
        __syncthreads();
        if (s_flag) {
            __threadfence();                   // acquire other blocks' tile stores
            act_slab(m * 128, bihf, bhhf, bihb, bhhb);
            __syncthreads();
            feats_slab(m * 128, Wt, bt, es, ws);
            feats_slab(m * 128 + 64, Wt, bt, es, ws);
            __syncthreads();
            if (threadIdx.x == 0) {
                __threadfence();               // release feats
                atomicExch(&g_slab_ready[m], 1);
            }
        }
        __syncthreads();
    }
}

// ---------------- parallel backpointer recompute ----------------
__global__ void __launch_bounds__(256) k_bp(const float* __restrict__ trans)
{
    __shared__ float trs[TT * TT];
    const int lt = threadIdx.x;
    const int wy = threadIdx.y;
    const int tid = wy * 32 + lt;
    for (int i = tid; i < TT * TT; i += 256) trs[i] = trans[i];
    __syncthreads();

    const int t = blockIdx.x * 8 + wy;
    const int j = lt;
    const bool act = (j < TT);
    float fvl = (lt < TT) ? g_fv[(size_t)t * TT + lt] : NEGV;

    float ss[TT];
    int ii[TT];
#pragma unroll
    for (int i = 0; i < TT; i++) {
        float v = __shfl_sync(0xffffffffu, fvl, i);
        ss[i] = v + (act ? trs[j * TT + i] : 0.0f);
        ii[i] = i;
    }
#define CMB(d, a, b) { bool p = ss[b] > ss[a]; ss[d] = p ? ss[b] : ss[a]; ii[d] = p ? ii[b] : ii[a]; }
#pragma unroll
    for (int q = 0; q < 10; q++) CMB(q, 2 * q, 2 * q + 1);
#pragma unroll
    for (int q = 0; q < 5; q++)  CMB(q, 2 * q, 2 * q + 1);
    CMB(0, 0, 1); CMB(1, 2, 3); ss[2] = ss[4]; ii[2] = ii[4];
    CMB(0, 0, 1); ss[1] = ss[2]; ii[1] = ii[2];
    CMB(0, 0, 1);
#undef CMB
    if (act) g_bp[(size_t)t * TT + j] = (unsigned char)ii[0];
}

// ---------------- backtrack: chunk candidates + maps ----------------
__global__ void k_bt1()
{
    __shared__ unsigned char bl[128 * TT];
    const int c = blockIdx.x;
    const int t0 = c * 128;
    const u32* src = (const u32*)(g_bp + (size_t)t0 * TT);
    u32* dst = (u32*)bl;
    for (int i = threadIdx.x; i < 640; i += 32) dst[i] = src[i];
    __syncwarp();
    int s = threadIdx.x;
    if (s < TT) {
        int cur = s;
        unsigned char* cand = g_cand + ((size_t)c * TT + s) * 128;
        cand[127] = (unsigned char)cur;
        for (int r = 127; r >= 1; r--) {
            cur = bl[r * TT + cur];
            cand[r - 1] = (unsigned char)cur;
        }
        g_map[c * TT + s] = bl[cur];
    }
}

__global__ void k_bt2()
{
    __shared__ unsigned char mp[128 * TT];
    u32* dst = (u32*)mp;
    const u32* src = (const u32*)g_map;
    for (int i = threadIdx.x; i < 640; i += 32) dst[i] = src[i];
    __syncwarp();
    if (threadIdx.x == 0) {
        int e = g_best;
        g_ent[127] = e;
        for (int c = 127; c >= 1; c--) {
            e = mp[c * TT + e];
            g_ent[c - 1] = e;
        }
    }
}

__global__ void k_bt3(float* __restrict__ out, int off)
{
    int c = blockIdx.x, r = threadIdx.x;
    int e = g_ent[c];
    out[off + c * 128 + r] = (float)g_cand[((size_t)c * TT + e) * 128 + r];
}

// ---------------- launcher ----------------
extern "C" void kernel_launch(void* const* d_in, const int* in_sizes, int n_in,
                              void* d_out, int out_size)
{
    const float* x     = (const float*)d_in[0];
    const float* wihf  = (const float*)d_in[1];
    const float* bihf  = (const float*)d_in[3];
    const float* bhhf  = (const float*)d_in[4];
    const float* wihb  = (const float*)d_in[5];
    const float* bihb  = (const float*)d_in[7];
    const float* bhhb  = (const float*)d_in[8];
    const float* wtag  = (const float*)d_in[9];
    const float* btag  = (const float*)d_in[10];
    const float* trans = (const float*)d_in[11];
    float* out = (float*)d_out;

    int off = (out_size >= SEQ + 1) ? 1 : 0;

    k_init<<<1, 128>>>();
    k_fused<<<297, 256>>>(x + 768, wihf, wihb, bihf, bhhf, bihb, bhhb,
                          wtag, btag, trans, out, off);
    k_bp<<<SEQ / 8, dim3(32, 8)>>>(trans);
    k_bt1<<<128, 32>>>();
    k_bt2<<<1, 32>>>();
    k_bt3<<<128, 128>>>(out, off);
}